// round 2
// baseline (speedup 1.0000x reference)
#include <cuda_runtime.h>

// Problem maxima (actual sizes read from in_sizes at runtime).
#define NN 100000
#define EE 1600000
#define BLK 256

// ---- device scratch (no allocations allowed) ----
__device__ int2   g_edge[EE];      // packed {src, dst} int32
__device__ float  g_dinv[NN];      // degree (incl. self loop) -> rsqrt in place
__device__ float  g_px[NN];        // dinv[v] * x[v]
__device__ float  g_s[NN];         // layer-1 scalar aggregate
__device__ float2 g_pq[NN];        // dinv[v] * (max(s,0), min(s,0))
__device__ float  g_PQ[2 * NN];    // layer-2 (P,Q) aggregate
__device__ float  g_agg[NN * 16];  // general-path 16-wide aggregate (fallback)
__device__ float  g_c[64];         // c1[32] = relu(W1)@W2, c2[32] = min(W1,0)@W2
__device__ int    g_b1zero;
__device__ int    g_is64;          // edge dtype probe result

// ---- probe: is the edge buffer int64 or int32? ----
__global__ void k_detect(const void* __restrict__ ei, int E, int N) {
    __shared__ int bad;
    if (threadIdx.x == 0) bad = 0;
    __syncthreads();
    const long long* p = (const long long*)ei;
    int idx = threadIdx.x;             // probe first 256 int64 slots (in-bounds either way)
    if (idx < E) {
        long long v = p[idx];
        if (v < 0 || v >= (long long)N) atomicExch(&bad, 1);
    }
    __syncthreads();
    if (threadIdx.x == 0) g_is64 = !bad;
}

// ---- tiny prep: fused coefficients + b1-zero flag ----
__global__ void k_prep(const float* __restrict__ W1, const float* __restrict__ b1,
                       const float* __restrict__ W2) {
    int j = threadIdx.x;  // 0..31
    float c1 = 0.f, c2 = 0.f;
#pragma unroll
    for (int k = 0; k < 16; k++) {
        float w  = W1[k];
        float wv = W2[k * 32 + j];
        c1 += fmaxf(w, 0.f) * wv;
        c2 += fminf(w, 0.f) * wv;
    }
    g_c[j] = c1;
    g_c[32 + j] = c2;
    if (j == 0) {
        int z = 1;
        for (int k = 0; k < 16; k++)
            if (b1[k] != 0.f) z = 0;
        g_b1zero = z;
    }
}

// ---- init: degree = 1 (self loop); zero 16-wide agg only if fallback needed ----
__global__ void k_init(int n) {
    int i = blockIdx.x * blockDim.x + threadIdx.x;
    if (i < n) g_dinv[i] = 1.0f;
    if (!g_b1zero && i < n * 16) g_agg[i] = 0.0f;
}

// ---- pass 1: edge convert/pack + degree atomics (4 edges/thread) ----
__global__ void k_edges(const void* __restrict__ eiv, int E) {
    int i  = blockIdx.x * blockDim.x + threadIdx.x;
    int e0 = 4 * i;
    if (e0 >= E) return;
    int is64 = g_is64;
    int s[4], d[4];
    int cnt = min(4, E - e0);
    if (cnt == 4) {
        if (is64) {
            const long long* ei = (const long long*)eiv;
            longlong2 s01 = *reinterpret_cast<const longlong2*>(ei + e0);
            longlong2 s23 = *reinterpret_cast<const longlong2*>(ei + e0 + 2);
            longlong2 d01 = *reinterpret_cast<const longlong2*>(ei + E + e0);
            longlong2 d23 = *reinterpret_cast<const longlong2*>(ei + E + e0 + 2);
            s[0] = (int)s01.x; s[1] = (int)s01.y; s[2] = (int)s23.x; s[3] = (int)s23.y;
            d[0] = (int)d01.x; d[1] = (int)d01.y; d[2] = (int)d23.x; d[3] = (int)d23.y;
        } else {
            const int* ei = (const int*)eiv;
            int4 sv = *reinterpret_cast<const int4*>(ei + e0);
            int4 dv = *reinterpret_cast<const int4*>(ei + E + e0);
            s[0] = sv.x; s[1] = sv.y; s[2] = sv.z; s[3] = sv.w;
            d[0] = dv.x; d[1] = dv.y; d[2] = dv.z; d[3] = dv.w;
        }
        int4 p0 = make_int4(s[0], d[0], s[1], d[1]);
        int4 p1 = make_int4(s[2], d[2], s[3], d[3]);
        *reinterpret_cast<int4*>(&g_edge[e0])     = p0;
        *reinterpret_cast<int4*>(&g_edge[e0 + 2]) = p1;
#pragma unroll
        for (int j = 0; j < 4; j++) atomicAdd(&g_dinv[d[j]], 1.0f);
    } else {
        for (int j = 0; j < cnt; j++) {
            int sj, dj;
            if (is64) {
                const long long* ei = (const long long*)eiv;
                sj = (int)ei[e0 + j]; dj = (int)ei[E + e0 + j];
            } else {
                const int* ei = (const int*)eiv;
                sj = ei[e0 + j]; dj = ei[E + e0 + j];
            }
            g_edge[e0 + j] = make_int2(sj, dj);
            atomicAdd(&g_dinv[dj], 1.0f);
        }
    }
}

// ---- pass 2: dinv = rsqrt(deg); px = dinv*x; s init = self-loop term ----
__global__ void k_node1(const float* __restrict__ x, int n) {
    int v = blockIdx.x * blockDim.x + threadIdx.x;
    if (v >= n) return;
    float dv  = rsqrtf(g_dinv[v]);
    g_dinv[v] = dv;
    float pxv = dv * x[v];
    g_px[v]   = pxv;
    g_s[v]    = dv * pxv;  // dinv^2 * x  (self-loop contribution)
}

// ---- pass 3: layer-1 scalar scatter: s[dst] += dinv[dst]*px[src] ----
__global__ void k_scat1(int E) {
    int i = blockIdx.x * blockDim.x + threadIdx.x;
    if (i >= E) return;
    int2 e = g_edge[i];
    float contrib = __ldg(&g_dinv[e.y]) * __ldg(&g_px[e.x]);
    atomicAdd(&g_s[e.y], contrib);
}

// ---- pass 4: p/q split; PQ init = self-loop term ----
__global__ void k_node2(int n) {
    int v = blockIdx.x * blockDim.x + threadIdx.x;
    if (v >= n) return;
    float sv = g_s[v];
    float dv = g_dinv[v];
    float p = fmaxf(sv, 0.f), q = fminf(sv, 0.f);
    g_pq[v] = make_float2(dv * p, dv * q);
    g_PQ[2 * v]     = dv * dv * p;
    g_PQ[2 * v + 1] = dv * dv * q;
}

// ---- pass 5: layer-2 scatter. Fast path: 2 scalar REDs. Fallback: 16-wide. ----
__global__ void k_scat2(const float* __restrict__ W1, const float* __restrict__ b1, int E) {
    __shared__ float sW1[16], sb1[16];
    if (threadIdx.x < 16) {
        sW1[threadIdx.x] = W1[threadIdx.x];
        sb1[threadIdx.x] = b1[threadIdx.x];
    }
    __syncthreads();
    int bz = g_b1zero;
    int i = blockIdx.x * blockDim.x + threadIdx.x;
    if (i >= E) return;
    int2 e = g_edge[i];
    float dvd = __ldg(&g_dinv[e.y]);
    if (bz) {
        float2 t = __ldg(&g_pq[e.x]);
        atomicAdd(&g_PQ[2 * e.y],     dvd * t.x);
        atomicAdd(&g_PQ[2 * e.y + 1], dvd * t.y);
    } else {
        float sv   = __ldg(&g_s[e.x]);
        float norm = __ldg(&g_dinv[e.x]) * dvd;
#pragma unroll
        for (int k = 0; k < 16; k++) {
            float h = fmaxf(sv * sW1[k] + sb1[k], 0.f);
            atomicAdd(&g_agg[e.y * 16 + k], norm * h);
        }
    }
}

// ---- pass 6: output projection ----
__global__ void k_out(const float* __restrict__ W1, const float* __restrict__ b1,
                      const float* __restrict__ W2, const float* __restrict__ b2,
                      float* __restrict__ out, int n) {
    __shared__ float sc[64];
    __shared__ float sb2[32];
    __shared__ float sW2[512];
    __shared__ float sW1[16], sb1[16];
    int bz = g_b1zero;
    int t = threadIdx.x;
    if (t < 64) sc[t] = g_c[t];
    if (t < 32) sb2[t] = b2[t];
    if (!bz) {
        for (int k = t; k < 512; k += blockDim.x) sW2[k] = W2[k];
        if (t < 16) { sW1[t] = W1[t]; sb1[t] = b1[t]; }
    }
    __syncthreads();
    int v = blockIdx.x * blockDim.x + t;
    if (v >= n) return;

    float o[32];
    if (bz) {
        float P = g_PQ[2 * v], Q = g_PQ[2 * v + 1];
#pragma unroll
        for (int j = 0; j < 32; j++) o[j] = P * sc[j] + Q * sc[32 + j] + sb2[j];
    } else {
        float sv = g_s[v], dv = g_dinv[v];
        float n2 = dv * dv;
        float tot[16];
#pragma unroll
        for (int k = 0; k < 16; k++) {
            float h = fmaxf(sv * sW1[k] + sb1[k], 0.f);
            tot[k] = g_agg[v * 16 + k] + n2 * h;
        }
#pragma unroll
        for (int j = 0; j < 32; j++) {
            float acc = sb2[j];
#pragma unroll
            for (int k = 0; k < 16; k++) acc += tot[k] * sW2[k * 32 + j];
            o[j] = acc;
        }
    }
    float4* po = reinterpret_cast<float4*>(out + (size_t)v * 32);
#pragma unroll
    for (int j = 0; j < 8; j++)
        po[j] = make_float4(o[4 * j], o[4 * j + 1], o[4 * j + 2], o[4 * j + 3]);
}

extern "C" void kernel_launch(void* const* d_in, const int* in_sizes, int n_in,
                              void* d_out, int out_size) {
    const float* x  = (const float*)d_in[0];
    const void*  ei = d_in[1];
    const float* W1 = (const float*)d_in[2];
    const float* b1 = (const float*)d_in[3];
    const float* W2 = (const float*)d_in[4];
    const float* b2 = (const float*)d_in[5];
    float* out = (float*)d_out;

    int N = in_sizes[0];
    int E = in_sizes[1] / 2;

    int gN   = (N + BLK - 1) / BLK;
    int g16N = (16 * N + BLK - 1) / BLK;
    int gE   = (E + BLK - 1) / BLK;
    int gE4  = ((E + 3) / 4 + BLK - 1) / BLK;

    k_detect<<<1, 256>>>(ei, E, N);
    k_prep<<<1, 32>>>(W1, b1, W2);
    k_init<<<g16N, BLK>>>(N);
    k_edges<<<gE4, BLK>>>(ei, E);
    k_node1<<<gN, BLK>>>(x, N);
    k_scat1<<<gE, BLK>>>(E);
    k_node2<<<gN, BLK>>>(N);
    k_scat2<<<gE, BLK>>>(W1, b1, E);
    k_out<<<gN, BLK>>>(W1, b1, W2, b2, out, N);
}

// round 3
// speedup vs baseline: 1.2494x; 1.2494x over previous
#include <cuda_runtime.h>

#define NN 100000
#define EE 1600000
#define BLK 256

// ---- device scratch (no allocations allowed) ----
__device__ int    g_src32[EE];     // int64->int32 converted edges (only if needed)
__device__ int    g_dst32[EE];
__device__ float  g_deg[NN];       // raw in-degree (self loop added later)
__device__ float  g_dinv[NN];
__device__ float  g_px[NN];        // dinv[v]*x[v]
__device__ float  g_s[NN];         // raw layer-1 aggregate, then finalized s
__device__ float2 g_pq[NN];        // dinv[v]*(max(s,0), min(s,0))
__device__ float2 g_PQ[NN];        // raw layer-2 (P,Q) aggregate (incl. self term)
__device__ float  g_agg[NN * 16];  // general-path fallback aggregate
__device__ float  g_c[64];         // c1[32]=relu(W1)@W2, c2[32]=min(W1,0)@W2
__device__ int    g_b1zero;
__device__ int    g_is64;

// ---- setup: dtype probe + fused coefficients + zero scratch ----
__global__ void k_setup(const void* __restrict__ ei, const float* __restrict__ W1,
                        const float* __restrict__ b1, const float* __restrict__ W2,
                        int E, int N) {
    int tid = threadIdx.x;
    if (blockIdx.x == 0) {
        __shared__ int bad;
        if (tid == 0) bad = 0;
        __syncthreads();
        const long long* p = (const long long*)ei;
        if (tid < E) {
            long long v = p[tid];  // in-bounds for both layouts (E>=256)
            if (v < 0 || v >= (long long)N) atomicExch(&bad, 1);
        }
        __syncthreads();
        if (tid == 0) {
            g_is64 = !bad;
            int z = 1;
            for (int k = 0; k < 16; k++)
                if (b1[k] != 0.f) z = 0;
            g_b1zero = z;
        }
        if (tid < 32) {
            float c1 = 0.f, c2 = 0.f;
#pragma unroll
            for (int k = 0; k < 16; k++) {
                float w  = W1[k];
                float wv = W2[k * 32 + tid];
                c1 += fmaxf(w, 0.f) * wv;
                c2 += fminf(w, 0.f) * wv;
            }
            g_c[tid] = c1;
            g_c[32 + tid] = c2;
        }
    }
    int v = blockIdx.x * BLK + tid;
    if (v < N) {
        g_deg[v] = 0.f;
        bool bz = true;  // local check (no cross-block race on g_b1zero)
#pragma unroll
        for (int k = 0; k < 16; k++)
            if (b1[k] != 0.f) bz = false;
        if (!bz) {
            float4 z = make_float4(0.f, 0.f, 0.f, 0.f);
            float4* a = reinterpret_cast<float4*>(&g_agg[v * 16]);
            a[0] = z; a[1] = z; a[2] = z; a[3] = z;
        }
    }
}

// ---- pass 1: degree atomics (+ one-time int64->int32 conversion) ----
__global__ void k_deg(const void* __restrict__ eiv, int E) {
    int i  = blockIdx.x * blockDim.x + threadIdx.x;
    int e0 = 4 * i;
    if (e0 >= E) return;
    if (g_is64) {
        const long long* ei = (const long long*)eiv;
        if (e0 + 3 < E) {
            longlong2 s01 = *reinterpret_cast<const longlong2*>(ei + e0);
            longlong2 s23 = *reinterpret_cast<const longlong2*>(ei + e0 + 2);
            longlong2 d01 = *reinterpret_cast<const longlong2*>(ei + E + e0);
            longlong2 d23 = *reinterpret_cast<const longlong2*>(ei + E + e0 + 2);
            int4 sv = make_int4((int)s01.x, (int)s01.y, (int)s23.x, (int)s23.y);
            int4 dv = make_int4((int)d01.x, (int)d01.y, (int)d23.x, (int)d23.y);
            *reinterpret_cast<int4*>(&g_src32[e0]) = sv;
            *reinterpret_cast<int4*>(&g_dst32[e0]) = dv;
            atomicAdd(&g_deg[dv.x], 1.f);
            atomicAdd(&g_deg[dv.y], 1.f);
            atomicAdd(&g_deg[dv.z], 1.f);
            atomicAdd(&g_deg[dv.w], 1.f);
        } else {
            for (int e = e0; e < E; e++) {
                int s = (int)ei[e], d = (int)ei[E + e];
                g_src32[e] = s; g_dst32[e] = d;
                atomicAdd(&g_deg[d], 1.f);
            }
        }
    } else {
        const int* dst = (const int*)eiv + E;
        if (e0 + 3 < E) {
            int4 dv = *reinterpret_cast<const int4*>(dst + e0);
            atomicAdd(&g_deg[dv.x], 1.f);
            atomicAdd(&g_deg[dv.y], 1.f);
            atomicAdd(&g_deg[dv.z], 1.f);
            atomicAdd(&g_deg[dv.w], 1.f);
        } else {
            for (int e = e0; e < E; e++) atomicAdd(&g_deg[dst[e]], 1.f);
        }
    }
}

// ---- pass 2: dinv = rsqrt(deg+1); px; raw s init = self-loop term ----
__global__ void k_node1(const float* __restrict__ x, int n) {
    int v = blockIdx.x * blockDim.x + threadIdx.x;
    if (v >= n) return;
    float dv  = rsqrtf(g_deg[v] + 1.0f);
    g_dinv[v] = dv;
    float pxv = dv * x[v];
    g_px[v]   = pxv;
    g_s[v]    = pxv;  // self-loop contribution to raw sum
}

// ---- pass 3: layer-1 raw scatter: s_raw[dst] += px[src] (8 edges/thread) ----
__global__ void k_scat1(const void* __restrict__ eiv, int E) {
    const int* srcp = g_is64 ? g_src32 : (const int*)eiv;
    const int* dstp = g_is64 ? g_dst32 : (const int*)eiv + E;
    int e0 = 8 * (blockIdx.x * blockDim.x + threadIdx.x);
    if (e0 >= E) return;
    if (e0 + 7 < E) {
        int4 s0 = *reinterpret_cast<const int4*>(srcp + e0);
        int4 s1 = *reinterpret_cast<const int4*>(srcp + e0 + 4);
        int4 d0 = *reinterpret_cast<const int4*>(dstp + e0);
        int4 d1 = *reinterpret_cast<const int4*>(dstp + e0 + 4);
        float a0 = __ldg(&g_px[s0.x]), a1 = __ldg(&g_px[s0.y]);
        float a2 = __ldg(&g_px[s0.z]), a3 = __ldg(&g_px[s0.w]);
        float a4 = __ldg(&g_px[s1.x]), a5 = __ldg(&g_px[s1.y]);
        float a6 = __ldg(&g_px[s1.z]), a7 = __ldg(&g_px[s1.w]);
        atomicAdd(&g_s[d0.x], a0); atomicAdd(&g_s[d0.y], a1);
        atomicAdd(&g_s[d0.z], a2); atomicAdd(&g_s[d0.w], a3);
        atomicAdd(&g_s[d1.x], a4); atomicAdd(&g_s[d1.y], a5);
        atomicAdd(&g_s[d1.z], a6); atomicAdd(&g_s[d1.w], a7);
    } else {
        for (int e = e0; e < E; e++)
            atomicAdd(&g_s[dstp[e]], __ldg(&g_px[srcp[e]]));
    }
}

// ---- pass 4: finalize s; pq split; raw PQ init = self term ----
__global__ void k_node2(int n) {
    int v = blockIdx.x * blockDim.x + threadIdx.x;
    if (v >= n) return;
    float dv = g_dinv[v];
    float s  = dv * g_s[v];
    g_s[v]   = s;  // finalized (for fallback path)
    float p = fmaxf(s, 0.f), q = fminf(s, 0.f);
    float2 pq = make_float2(dv * p, dv * q);
    g_pq[v] = pq;
    g_PQ[v] = pq;  // self-loop contribution (scaled by dinv[v] in k_out)
}

__device__ __forceinline__ void red2(float2* addr, float2 v) {
    asm volatile("red.add.v2.f32 [%0], {%1, %2};"
                 :: "l"(addr), "f"(v.x), "f"(v.y) : "memory");
}

// ---- pass 5: layer-2 raw scatter (8 edges/thread). Fast: 1 v2 RED/edge. ----
__global__ void k_scat2(const float* __restrict__ W1, const float* __restrict__ b1, int E) {
    // note: int32-input case reads original buffers via pointers passed in eiv slot
    extern __shared__ float dummy[];  // unused
    (void)dummy;
    E = E;  // placeholder (real body in k_scat2_impl below)
}

__global__ void k_scat2_impl(const void* __restrict__ eiv,
                             const float* __restrict__ W1,
                             const float* __restrict__ b1, int E) {
    const int* srcp = g_is64 ? g_src32 : (const int*)eiv;
    const int* dstp = g_is64 ? g_dst32 : (const int*)eiv + E;
    int bz = g_b1zero;
    int e0 = 8 * (blockIdx.x * blockDim.x + threadIdx.x);
    if (e0 >= E) return;
    if (bz) {
        if (e0 + 7 < E) {
            int4 s0 = *reinterpret_cast<const int4*>(srcp + e0);
            int4 s1 = *reinterpret_cast<const int4*>(srcp + e0 + 4);
            int4 d0 = *reinterpret_cast<const int4*>(dstp + e0);
            int4 d1 = *reinterpret_cast<const int4*>(dstp + e0 + 4);
            float2 t0 = __ldg(&g_pq[s0.x]), t1 = __ldg(&g_pq[s0.y]);
            float2 t2 = __ldg(&g_pq[s0.z]), t3 = __ldg(&g_pq[s0.w]);
            float2 t4 = __ldg(&g_pq[s1.x]), t5 = __ldg(&g_pq[s1.y]);
            float2 t6 = __ldg(&g_pq[s1.z]), t7 = __ldg(&g_pq[s1.w]);
            red2(&g_PQ[d0.x], t0); red2(&g_PQ[d0.y], t1);
            red2(&g_PQ[d0.z], t2); red2(&g_PQ[d0.w], t3);
            red2(&g_PQ[d1.x], t4); red2(&g_PQ[d1.y], t5);
            red2(&g_PQ[d1.z], t6); red2(&g_PQ[d1.w], t7);
        } else {
            for (int e = e0; e < E; e++) red2(&g_PQ[dstp[e]], __ldg(&g_pq[srcp[e]]));
        }
    } else {
        __shared__ float sW1[16], sb1[16];
        if (threadIdx.x < 16) { sW1[threadIdx.x] = W1[threadIdx.x]; sb1[threadIdx.x] = b1[threadIdx.x]; }
        __syncthreads();
        int eEnd = min(e0 + 8, E);
        for (int e = e0; e < eEnd; e++) {
            int s = srcp[e], d = dstp[e];
            float sv = __ldg(&g_s[s]);
            float ns = __ldg(&g_dinv[s]);  // dst scale deferred to k_out
#pragma unroll
            for (int k = 0; k < 16; k++) {
                float h = fmaxf(sv * sW1[k] + sb1[k], 0.f);
                atomicAdd(&g_agg[d * 16 + k], ns * h);
            }
        }
    }
}

// ---- pass 6: output projection ----
__global__ void k_out(const float* __restrict__ W1, const float* __restrict__ b1,
                      const float* __restrict__ W2, const float* __restrict__ b2,
                      float* __restrict__ out, int n) {
    __shared__ float sc[64];
    __shared__ float sb2[32];
    __shared__ float sW2[512];
    __shared__ float sW1[16], sb1[16];
    int bz = g_b1zero;
    int t = threadIdx.x;
    if (t < 64) sc[t] = g_c[t];
    if (t < 32) sb2[t] = b2[t];
    if (!bz) {
        for (int k = t; k < 512; k += blockDim.x) sW2[k] = W2[k];
        if (t < 16) { sW1[t] = W1[t]; sb1[t] = b1[t]; }
    }
    __syncthreads();
    int v = blockIdx.x * blockDim.x + t;
    if (v >= n) return;

    float o[32];
    float dv = g_dinv[v];
    if (bz) {
        float2 PQ = g_PQ[v];
        float P = dv * PQ.x, Q = dv * PQ.y;
#pragma unroll
        for (int j = 0; j < 32; j++) o[j] = P * sc[j] + Q * sc[32 + j] + sb2[j];
    } else {
        float sv = g_s[v];
        float n2 = dv * dv;
        float tot[16];
#pragma unroll
        for (int k = 0; k < 16; k++) {
            float h = fmaxf(sv * sW1[k] + sb1[k], 0.f);
            tot[k] = dv * g_agg[v * 16 + k] + n2 * h;
        }
#pragma unroll
        for (int j = 0; j < 32; j++) {
            float acc = sb2[j];
#pragma unroll
            for (int k = 0; k < 16; k++) acc += tot[k] * sW2[k * 32 + j];
            o[j] = acc;
        }
    }
    float4* po = reinterpret_cast<float4*>(out + (size_t)v * 32);
#pragma unroll
    for (int j = 0; j < 8; j++)
        po[j] = make_float4(o[4 * j], o[4 * j + 1], o[4 * j + 2], o[4 * j + 3]);
}

extern "C" void kernel_launch(void* const* d_in, const int* in_sizes, int n_in,
                              void* d_out, int out_size) {
    const float* x  = (const float*)d_in[0];
    const void*  ei = d_in[1];
    const float* W1 = (const float*)d_in[2];
    const float* b1 = (const float*)d_in[3];
    const float* W2 = (const float*)d_in[4];
    const float* b2 = (const float*)d_in[5];
    float* out = (float*)d_out;

    int N = in_sizes[0];
    int E = in_sizes[1] / 2;

    int gN  = (N + BLK - 1) / BLK;
    int gE4 = ((E + 3) / 4 + BLK - 1) / BLK;
    int gE8 = ((E + 7) / 8 + BLK - 1) / BLK;

    k_setup<<<gN, BLK>>>(ei, W1, b1, W2, E, N);
    k_deg<<<gE4, BLK>>>(ei, E);
    k_node1<<<gN, BLK>>>(x, N);
    k_scat1<<<gE8, BLK>>>(ei, E);
    k_node2<<<gN, BLK>>>(N);
    k_scat2_impl<<<gE8, BLK>>>(ei, W1, b1, E);
    k_out<<<gN, BLK>>>(W1, b1, W2, b2, out, N);
}